// round 7
// baseline (speedup 1.0000x reference)
#include <cuda_runtime.h>

#define NN 100000
#define EE 1600000
#define DD 128
#define STAT_BLOCKS 500   // NN / 200 rows per block

// ---------------- scratch (device globals: no allocation allowed) ----------------
__device__ __align__(16) float g_deg[NN];            // degree -> dinv (in place)
__device__ __align__(16) float g_val[EE];            // edge weights
__device__ __align__(16) float g_h[NN * DD];         // current activations
__device__ __align__(16) float g_x0[NN * DD];        // first embedding (residual)
__device__ __align__(16) float g_tmp[NN * DD];       // GEMM output (pre-BN)
__device__ __align__(16) float g_agg[NN * DD];       // SPMM accumulator
__device__ __align__(16) float g_part[STAT_BLOCKS * 256]; // per-block [sum(128) | sumsq(128)]
__device__ __align__(16) float g_scale[DD];
__device__ __align__(16) float g_shift[DD];

// ---------------- degree / edge value ----------------
__global__ void zero_deg_kernel() {
    int i = blockIdx.x * blockDim.x + threadIdx.x;
    if (i < NN) g_deg[i] = 0.f;
}

__global__ void compute_deg_kernel(const int* __restrict__ col) {
    int e = blockIdx.x * blockDim.x + threadIdx.x;   // EE % 256 == 0
    atomicAdd(&g_deg[col[e]], 1.0f);
}

__global__ void dinv_kernel() {
    int i = blockIdx.x * blockDim.x + threadIdx.x;
    if (i < NN) {
        float d = g_deg[i];
        g_deg[i] = d > 0.f ? rsqrtf(d) : 0.f;
    }
}

__global__ void value_kernel(const int* __restrict__ row, const int* __restrict__ col) {
    int e = blockIdx.x * blockDim.x + threadIdx.x;   // EE % 256 == 0
    g_val[e] = g_deg[col[e]] * g_deg[row[e]];
}

// ---------------- SPMM: agg[col] += val * h[row], one warp per edge ----------------
__global__ void __launch_bounds__(256) spmm_kernel(const int* __restrict__ row,
                                                   const int* __restrict__ col) {
    int e = blockIdx.x * 8 + (threadIdx.x >> 5);     // EE % 8 == 0 in grid
    int lane = threadIdx.x & 31;
    int r = __ldg(row + e);
    int c = __ldg(col + e);
    float v = g_val[e];
    float4 hv = ((const float4*)g_h)[r * 32 + lane];
    float4 o;
    o.x = hv.x * v; o.y = hv.y * v; o.z = hv.z * v; o.w = hv.w * v;
    atomicAdd(((float4*)g_agg) + c * 32 + lane, o);  // vector red, sm_90+
}

__global__ void zero_agg_kernel() {
    int i = blockIdx.x * blockDim.x + threadIdx.x;   // NN*32 float4s
    ((float4*)g_agg)[i] = make_float4(0.f, 0.f, 0.f, 0.f);
}

// ---------------- 128-wide SGEMM: g_tmp = A @ W^T + bias ----------------
// A: [NN,128] (either external x or g_agg). W: [128,128] row-major [n][k].
// Block = 64 rows x 128 cols, 256 threads, thread tile 8 rows x 4 cols.
__global__ void __launch_bounds__(256) gemm128_kernel(const float* __restrict__ Aext,
                                                      int useAgg,
                                                      const float* __restrict__ W,
                                                      const float* __restrict__ bias) {
    extern __shared__ float sh[];
    float* xs = sh;               // 64*128
    float* ws = sh + 64 * 128;    // 128*129 (transposed, padded: ws[k*129+n])
    const float* A = useAgg ? g_agg : Aext;
    int tid = threadIdx.x;
    int rowBase = blockIdx.x * 64;

#pragma unroll
    for (int i = 0; i < 64; i++) {        // stage W transposed (conflict-free: stride 129)
        int idx = i * 256 + tid;
        ws[(idx & 127) * 129 + (idx >> 7)] = W[idx];
    }
#pragma unroll
    for (int i = 0; i < 32; i++) {        // stage A tile (natural layout)
        int idx = i * 256 + tid;
        int r = rowBase + (idx >> 7);
        xs[idx] = (r < NN) ? A[r * DD + (idx & 127)] : 0.f;
    }
    __syncthreads();

    int tx = tid & 31;        // col group: cols tx, tx+32, tx+64, tx+96
    int ty = tid >> 5;        // row group: rows ty*8 .. ty*8+7
    float acc[8][4];
#pragma unroll
    for (int j = 0; j < 8; j++) { acc[j][0] = acc[j][1] = acc[j][2] = acc[j][3] = 0.f; }

    const float4* xs4 = (const float4*)xs + ty * 8 * 32;
    for (int k4 = 0; k4 < 32; k4++) {
        float w[4][4];
#pragma unroll
        for (int kk = 0; kk < 4; kk++) {
            const float* wr = ws + (k4 * 4 + kk) * 129 + tx;
            w[kk][0] = wr[0]; w[kk][1] = wr[32]; w[kk][2] = wr[64]; w[kk][3] = wr[96];
        }
#pragma unroll
        for (int j = 0; j < 8; j++) {
            float4 xv = xs4[j * 32 + k4];   // broadcast within warp (same ty, same k4)
            acc[j][0] += xv.x * w[0][0]; acc[j][1] += xv.x * w[0][1];
            acc[j][2] += xv.x * w[0][2]; acc[j][3] += xv.x * w[0][3];
            acc[j][0] += xv.y * w[1][0]; acc[j][1] += xv.y * w[1][1];
            acc[j][2] += xv.y * w[1][2]; acc[j][3] += xv.y * w[1][3];
            acc[j][0] += xv.z * w[2][0]; acc[j][1] += xv.z * w[2][1];
            acc[j][2] += xv.z * w[2][2]; acc[j][3] += xv.z * w[2][3];
            acc[j][0] += xv.w * w[3][0]; acc[j][1] += xv.w * w[3][1];
            acc[j][2] += xv.w * w[3][2]; acc[j][3] += xv.w * w[3][3];
        }
    }

    float b0 = __ldg(bias + tx), b1 = __ldg(bias + tx + 32);
    float b2 = __ldg(bias + tx + 64), b3 = __ldg(bias + tx + 96);
#pragma unroll
    for (int j = 0; j < 8; j++) {
        int r = rowBase + ty * 8 + j;
        if (r < NN) {
            float* o = g_tmp + r * DD + tx;
            o[0] = acc[j][0] + b0; o[32] = acc[j][1] + b1;
            o[64] = acc[j][2] + b2; o[96] = acc[j][3] + b3;
        }
    }
}

// ---------------- BN stats (two-stage, no atomics) ----------------
__global__ void col_stats_kernel() {
    int c = threadIdx.x;                 // 128 threads, one per column
    int r0 = blockIdx.x * 200;           // NN / STAT_BLOCKS
    float s = 0.f, s2 = 0.f;
    for (int r = r0; r < r0 + 200; r++) {
        float v = g_tmp[r * DD + c];
        s += v; s2 += v * v;
    }
    g_part[blockIdx.x * 256 + c] = s;
    g_part[blockIdx.x * 256 + 128 + c] = s2;
}

__global__ void bn_finalize_kernel(const float* __restrict__ gamma,
                                   const float* __restrict__ beta) {
    int c = threadIdx.x;                 // 128 threads
    float s = 0.f, s2 = 0.f;
    for (int b = 0; b < STAT_BLOCKS; b++) {
        s += g_part[b * 256 + c];
        s2 += g_part[b * 256 + 128 + c];
    }
    const float invM = 1.0f / (float)NN;
    float mu = s * invM;
    float var = s2 * invM - mu * mu;
    float sc = gamma[c] * rsqrtf(var + 1e-5f);
    g_scale[c] = sc;
    g_shift[c] = beta[c] - mu * sc;
}

// ---------------- BN apply + relu (+ residual) ----------------
__global__ void bn_apply_kernel(int addRes) {
    int i = blockIdx.x * blockDim.x + threadIdx.x;   // NN*32 float4s exactly
    int c4 = i & 31;
    float4 v = ((const float4*)g_tmp)[i];
    float4 sc = ((const float4*)g_scale)[c4];
    float4 shv = ((const float4*)g_shift)[c4];
    v.x = fmaxf(v.x * sc.x + shv.x, 0.f);
    v.y = fmaxf(v.y * sc.y + shv.y, 0.f);
    v.z = fmaxf(v.z * sc.z + shv.z, 0.f);
    v.w = fmaxf(v.w * sc.w + shv.w, 0.f);
    if (addRes) {
        float4 x0 = ((const float4*)g_x0)[i];
        v.x += x0.x; v.y += x0.y; v.z += x0.z; v.w += x0.w;
    } else {
        ((float4*)g_x0)[i] = v;          // first layer: capture residual
    }
    ((float4*)g_h)[i] = v;
}

// ---------------- classifier: out = g_h @ cls_w^T + cls_b, [NN,40] ----------------
// Block = 64 rows x 40 cols, 256 threads; thread tile 2 rows x 5 cols.
__global__ void __launch_bounds__(256) gemm_cls_kernel(const float* __restrict__ W,
                                                       const float* __restrict__ bias,
                                                       float* __restrict__ out) {
    extern __shared__ float sh[];
    float* xs = sh;               // 64*132 (padded)
    float* ws = sh + 64 * 132;    // 128*40 (transposed: ws[k*40+c])
    int tid = threadIdx.x;
    int rowBase = blockIdx.x * 64;

#pragma unroll
    for (int i = 0; i < 20; i++) {        // 40*128 = 5120 = 20*256
        int idx = i * 256 + tid;
        ws[(idx & 127) * 40 + (idx >> 7)] = W[idx];
    }
#pragma unroll
    for (int i = 0; i < 32; i++) {
        int idx = i * 256 + tid;
        int r = rowBase + (idx >> 7);
        xs[(idx >> 7) * 132 + (idx & 127)] = (r < NN) ? g_h[r * DD + (idx & 127)] : 0.f;
    }
    __syncthreads();

    int tx = tid & 7;     // cols tx + 8*c, c in [0,5)
    int ty = tid >> 3;    // rows ty*2, ty*2+1
    float acc[2][5];
#pragma unroll
    for (int j = 0; j < 2; j++)
#pragma unroll
        for (int c = 0; c < 5; c++) acc[j][c] = 0.f;

    const float* x0p = xs + (ty * 2) * 132;
    const float* x1p = x0p + 132;
#pragma unroll 4
    for (int k = 0; k < 128; k++) {
        float xv0 = x0p[k], xv1 = x1p[k];
        const float* wr = ws + k * 40 + tx;
#pragma unroll
        for (int c = 0; c < 5; c++) {
            float wv = wr[8 * c];
            acc[0][c] += xv0 * wv;
            acc[1][c] += xv1 * wv;
        }
    }
#pragma unroll
    for (int j = 0; j < 2; j++) {
        int r = rowBase + ty * 2 + j;
        if (r < NN) {
#pragma unroll
            for (int c = 0; c < 5; c++) {
                int colI = tx + 8 * c;
                out[r * 40 + colI] = acc[j][c] + __ldg(bias + colI);
            }
        }
    }
}

// ---------------- launch ----------------
extern "C" void kernel_launch(void* const* d_in, const int* in_sizes, int n_in,
                              void* d_out, int out_size) {
    const float* x     = (const float*)d_in[0];
    const int*   ei    = (const int*)d_in[1];
    const float* fc_w  = (const float*)d_in[2];
    const float* fc_b  = (const float*)d_in[3];
    const float* convw = (const float*)d_in[4];
    const float* convb = (const float*)d_in[5];
    const float* gamma = (const float*)d_in[6];
    const float* beta  = (const float*)d_in[7];
    const float* clsw  = (const float*)d_in[8];
    const float* clsb  = (const float*)d_in[9];
    float* out = (float*)d_out;
    const int* row = ei;        // edge_index[0]
    const int* col = ei + EE;   // edge_index[1]

    const int smem_gemm = (64 * 128 + 128 * 129) * 4;   // 98816 B
    const int smem_cls  = (64 * 132 + 128 * 40) * 4;    // 54272 B
    cudaFuncSetAttribute(gemm128_kernel, cudaFuncAttributeMaxDynamicSharedMemorySize, smem_gemm);
    cudaFuncSetAttribute(gemm_cls_kernel, cudaFuncAttributeMaxDynamicSharedMemorySize, smem_cls);

    // edge normalization weights
    zero_deg_kernel<<<(NN + 1023) / 1024, 1024>>>();
    compute_deg_kernel<<<EE / 256, 256>>>(col);
    dinv_kernel<<<(NN + 255) / 256, 256>>>();
    value_kernel<<<EE / 256, 256>>>(row, col);

    const int gB = (NN + 63) / 64;          // 1563
    const int eltB = NN * 32 / 256;         // 12500

    // input projection + BN + relu, capture x0
    gemm128_kernel<<<gB, 256, smem_gemm>>>(x, 0, fc_w, fc_b);
    col_stats_kernel<<<STAT_BLOCKS, 128>>>();
    bn_finalize_kernel<<<1, 128>>>(gamma, beta);
    bn_apply_kernel<<<eltB, 256>>>(0);

    for (int l = 0; l < 3; l++) {
        zero_agg_kernel<<<eltB, 256>>>();
        spmm_kernel<<<EE / 8, 256>>>(row, col);
        gemm128_kernel<<<gB, 256, smem_gemm>>>(nullptr, 1, convw + l * DD * DD, convb + l * DD);
        col_stats_kernel<<<STAT_BLOCKS, 128>>>();
        bn_finalize_kernel<<<1, 128>>>(gamma + (l + 1) * DD, beta + (l + 1) * DD);
        bn_apply_kernel<<<eltB, 256>>>(1);
    }

    gemm_cls_kernel<<<gB, 256, smem_cls>>>(clsw, clsb, out);
}

// round 8
// speedup vs baseline: 1.5720x; 1.5720x over previous
#include <cuda_runtime.h>

#define NN 100000
#define EE 1600000
#define DD 128
#define STAT_BLOCKS 500   // NN / 200 rows per block
#define SCAN_NB 98        // ceil(NN / 1024)

// ---------------- scratch (device globals: no allocation allowed) ----------------
__device__ __align__(16) float g_deg[NN];            // dinv (float)
__device__ __align__(16) int   g_cnt[NN];            // int degree
__device__ __align__(16) int   g_offp[NN];           // per-block exclusive scan
__device__ __align__(16) int   g_off[NN + 1];        // CSR offsets
__device__ __align__(16) int   g_cur[NN];            // scatter cursors
__device__ __align__(16) int   g_bsum[128];          // scan block sums
__device__ __align__(16) int   g_bpre[128];          // scan block prefixes
__device__ __align__(16) int   g_eidx[EE];           // CSR: source row per slot
__device__ __align__(16) float g_eval[EE];           // CSR: edge weight per slot
__device__ __align__(16) float g_h[NN * DD];         // current activations
__device__ __align__(16) float g_x0[NN * DD];        // first embedding (residual)
__device__ __align__(16) float g_tmp[NN * DD];       // GEMM output (pre-BN)
__device__ __align__(16) float g_agg[NN * DD];       // SPMM output
__device__ __align__(16) float g_part[STAT_BLOCKS * 256]; // per-block [sum(128)|sumsq(128)]
__device__ __align__(16) float g_scale[DD];
__device__ __align__(16) float g_shift[DD];

// ---------------- degree ----------------
__global__ void zero_cnt_kernel() {
    int i = blockIdx.x * blockDim.x + threadIdx.x;
    if (i < NN) g_cnt[i] = 0;
}

__global__ void compute_cnt_kernel(const int* __restrict__ col) {
    int e = blockIdx.x * blockDim.x + threadIdx.x;   // EE % 256 == 0
    atomicAdd(&g_cnt[col[e]], 1);
}

__global__ void dinv_kernel() {
    int i = blockIdx.x * blockDim.x + threadIdx.x;
    if (i < NN) {
        int d = g_cnt[i];
        g_deg[i] = d > 0 ? rsqrtf((float)d) : 0.f;
    }
}

// ---------------- prefix scan (3 phases) ----------------
__global__ void __launch_bounds__(1024) scan1_kernel() {
    __shared__ int sh[1024];
    int i = blockIdx.x * 1024 + threadIdx.x;
    int v = (i < NN) ? g_cnt[i] : 0;
    sh[threadIdx.x] = v;
    __syncthreads();
#pragma unroll
    for (int off = 1; off < 1024; off <<= 1) {
        int t = 0;
        if (threadIdx.x >= off) t = sh[threadIdx.x - off];
        __syncthreads();
        sh[threadIdx.x] += t;
        __syncthreads();
    }
    if (i < NN) g_offp[i] = sh[threadIdx.x] - v;     // exclusive within block
    if (threadIdx.x == 1023) g_bsum[blockIdx.x] = sh[1023];
}

__global__ void scan2_kernel() {                     // 1 block, 128 threads
    __shared__ int sh[128];
    int t = threadIdx.x;
    int v = (t < SCAN_NB) ? g_bsum[t] : 0;
    sh[t] = v;
    __syncthreads();
#pragma unroll
    for (int off = 1; off < 128; off <<= 1) {
        int u = 0;
        if (t >= off) u = sh[t - off];
        __syncthreads();
        sh[t] += u;
        __syncthreads();
    }
    if (t < SCAN_NB) g_bpre[t] = sh[t] - v;          // exclusive
}

__global__ void scan3_kernel() {
    int i = blockIdx.x * blockDim.x + threadIdx.x;
    if (i < NN) {
        g_off[i] = g_offp[i] + g_bpre[i >> 10];
        g_cur[i] = 0;
    }
    if (i == 0) g_off[NN] = EE;
}

// ---------------- CSR scatter (sort edges by col) + weight ----------------
__global__ void scatter_kernel(const int* __restrict__ row, const int* __restrict__ col) {
    int e = blockIdx.x * blockDim.x + threadIdx.x;   // EE % 256 == 0
    int r = row[e];
    int c = col[e];
    int p = g_off[c] + atomicAdd(&g_cur[c], 1);
    g_eidx[p] = r;
    g_eval[p] = g_deg[c] * g_deg[r];
}

// ---------------- SPMM (gather, no atomics): one warp per destination node ----------------
__global__ void __launch_bounds__(256) spmm_csr_kernel() {
    int n = blockIdx.x * 8 + (threadIdx.x >> 5);     // grid covers NN exactly (NN % 8 == 0)
    int lane = threadIdx.x & 31;
    int s = g_off[n];
    int e = g_off[n + 1];
    float4 acc = make_float4(0.f, 0.f, 0.f, 0.f);
#pragma unroll 4
    for (int p = s; p < e; p++) {
        int r = __ldg(g_eidx + p);                   // warp-uniform broadcast
        float v = __ldg(g_eval + p);
        float4 hv = ((const float4*)g_h)[r * 32 + lane];
        acc.x += v * hv.x; acc.y += v * hv.y;
        acc.z += v * hv.z; acc.w += v * hv.w;
    }
    ((float4*)g_agg)[n * 32 + lane] = acc;
}

// ---------------- 128-wide SGEMM: g_tmp = A @ W^T + bias ----------------
__global__ void __launch_bounds__(256) gemm128_kernel(const float* __restrict__ Aext,
                                                      int useAgg,
                                                      const float* __restrict__ W,
                                                      const float* __restrict__ bias) {
    extern __shared__ float sh[];
    float* xs = sh;               // 64*128
    float* ws = sh + 64 * 128;    // 128*129 (transposed, padded: ws[k*129+n])
    const float* A = useAgg ? g_agg : Aext;
    int tid = threadIdx.x;
    int rowBase = blockIdx.x * 64;

#pragma unroll
    for (int i = 0; i < 64; i++) {        // stage W transposed (conflict-free: stride 129)
        int idx = i * 256 + tid;
        ws[(idx & 127) * 129 + (idx >> 7)] = W[idx];
    }
#pragma unroll
    for (int i = 0; i < 32; i++) {        // stage A tile
        int idx = i * 256 + tid;
        int r = rowBase + (idx >> 7);
        xs[idx] = (r < NN) ? A[r * DD + (idx & 127)] : 0.f;
    }
    __syncthreads();

    int tx = tid & 31;        // cols tx, tx+32, tx+64, tx+96
    int ty = tid >> 5;        // rows ty*8 .. ty*8+7
    float acc[8][4];
#pragma unroll
    for (int j = 0; j < 8; j++) { acc[j][0] = acc[j][1] = acc[j][2] = acc[j][3] = 0.f; }

    const float4* xs4 = (const float4*)xs + ty * 8 * 32;
    for (int k4 = 0; k4 < 32; k4++) {
        float w[4][4];
#pragma unroll
        for (int kk = 0; kk < 4; kk++) {
            const float* wr = ws + (k4 * 4 + kk) * 129 + tx;
            w[kk][0] = wr[0]; w[kk][1] = wr[32]; w[kk][2] = wr[64]; w[kk][3] = wr[96];
        }
#pragma unroll
        for (int j = 0; j < 8; j++) {
            float4 xv = xs4[j * 32 + k4];
            acc[j][0] += xv.x * w[0][0]; acc[j][1] += xv.x * w[0][1];
            acc[j][2] += xv.x * w[0][2]; acc[j][3] += xv.x * w[0][3];
            acc[j][0] += xv.y * w[1][0]; acc[j][1] += xv.y * w[1][1];
            acc[j][2] += xv.y * w[1][2]; acc[j][3] += xv.y * w[1][3];
            acc[j][0] += xv.z * w[2][0]; acc[j][1] += xv.z * w[2][1];
            acc[j][2] += xv.z * w[2][2]; acc[j][3] += xv.z * w[2][3];
            acc[j][0] += xv.w * w[3][0]; acc[j][1] += xv.w * w[3][1];
            acc[j][2] += xv.w * w[3][2]; acc[j][3] += xv.w * w[3][3];
        }
    }

    float b0 = __ldg(bias + tx), b1 = __ldg(bias + tx + 32);
    float b2 = __ldg(bias + tx + 64), b3 = __ldg(bias + tx + 96);
#pragma unroll
    for (int j = 0; j < 8; j++) {
        int r = rowBase + ty * 8 + j;
        if (r < NN) {
            float* o = g_tmp + r * DD + tx;
            o[0] = acc[j][0] + b0; o[32] = acc[j][1] + b1;
            o[64] = acc[j][2] + b2; o[96] = acc[j][3] + b3;
        }
    }
}

// ---------------- BN stats (two-stage, no atomics) ----------------
__global__ void col_stats_kernel() {
    int c = threadIdx.x;                 // 128 threads, one per column
    int r0 = blockIdx.x * 200;           // NN / STAT_BLOCKS
    float s = 0.f, s2 = 0.f;
    for (int r = r0; r < r0 + 200; r++) {
        float v = g_tmp[r * DD + c];
        s += v; s2 += v * v;
    }
    g_part[blockIdx.x * 256 + c] = s;
    g_part[blockIdx.x * 256 + 128 + c] = s2;
}

__global__ void bn_finalize_kernel(const float* __restrict__ gamma,
                                   const float* __restrict__ beta) {
    __shared__ float sh_s[512], sh_s2[512];
    int t = threadIdx.x;                 // 512 threads
    int c = t & 127, q = t >> 7;
    float s = 0.f, s2 = 0.f;
    for (int b = q; b < STAT_BLOCKS; b += 4) {
        s += g_part[b * 256 + c];
        s2 += g_part[b * 256 + 128 + c];
    }
    sh_s[t] = s; sh_s2[t] = s2;
    __syncthreads();
    if (q == 0) {
        s = sh_s[c] + sh_s[c + 128] + sh_s[c + 256] + sh_s[c + 384];
        s2 = sh_s2[c] + sh_s2[c + 128] + sh_s2[c + 256] + sh_s2[c + 384];
        const float invM = 1.0f / (float)NN;
        float mu = s * invM;
        float var = s2 * invM - mu * mu;
        float sc = gamma[c] * rsqrtf(var + 1e-5f);
        g_scale[c] = sc;
        g_shift[c] = beta[c] - mu * sc;
    }
}

// ---------------- BN apply + relu (+ residual) ----------------
__global__ void bn_apply_kernel(int addRes) {
    int i = blockIdx.x * blockDim.x + threadIdx.x;   // NN*32 float4s exactly
    int c4 = i & 31;
    float4 v = ((const float4*)g_tmp)[i];
    float4 sc = ((const float4*)g_scale)[c4];
    float4 shv = ((const float4*)g_shift)[c4];
    v.x = fmaxf(v.x * sc.x + shv.x, 0.f);
    v.y = fmaxf(v.y * sc.y + shv.y, 0.f);
    v.z = fmaxf(v.z * sc.z + shv.z, 0.f);
    v.w = fmaxf(v.w * sc.w + shv.w, 0.f);
    if (addRes) {
        float4 x0 = ((const float4*)g_x0)[i];
        v.x += x0.x; v.y += x0.y; v.z += x0.z; v.w += x0.w;
    } else {
        ((float4*)g_x0)[i] = v;          // first layer: capture residual
    }
    ((float4*)g_h)[i] = v;
}

// ---------------- classifier: out = g_h @ cls_w^T + cls_b, [NN,40] ----------------
__global__ void __launch_bounds__(256) gemm_cls_kernel(const float* __restrict__ W,
                                                       const float* __restrict__ bias,
                                                       float* __restrict__ out) {
    extern __shared__ float sh[];
    float* xs = sh;               // 64*132 (padded)
    float* ws = sh + 64 * 132;    // 128*40 (transposed: ws[k*40+c])
    int tid = threadIdx.x;
    int rowBase = blockIdx.x * 64;

#pragma unroll
    for (int i = 0; i < 20; i++) {        // 40*128 = 5120 = 20*256
        int idx = i * 256 + tid;
        ws[(idx & 127) * 40 + (idx >> 7)] = W[idx];
    }
#pragma unroll
    for (int i = 0; i < 32; i++) {
        int idx = i * 256 + tid;
        int r = rowBase + (idx >> 7);
        xs[(idx >> 7) * 132 + (idx & 127)] = (r < NN) ? g_h[r * DD + (idx & 127)] : 0.f;
    }
    __syncthreads();

    int tx = tid & 7;     // cols tx + 8*c
    int ty = tid >> 3;    // rows ty*2, ty*2+1
    float acc[2][5];
#pragma unroll
    for (int j = 0; j < 2; j++)
#pragma unroll
        for (int c = 0; c < 5; c++) acc[j][c] = 0.f;

    const float* x0p = xs + (ty * 2) * 132;
    const float* x1p = x0p + 132;
#pragma unroll 4
    for (int k = 0; k < 128; k++) {
        float xv0 = x0p[k], xv1 = x1p[k];
        const float* wr = ws + k * 40 + tx;
#pragma unroll
        for (int c = 0; c < 5; c++) {
            float wv = wr[8 * c];
            acc[0][c] += xv0 * wv;
            acc[1][c] += xv1 * wv;
        }
    }
#pragma unroll
    for (int j = 0; j < 2; j++) {
        int r = rowBase + ty * 2 + j;
        if (r < NN) {
#pragma unroll
            for (int c = 0; c < 5; c++) {
                int colI = tx + 8 * c;
                out[r * 40 + colI] = acc[j][c] + __ldg(bias + colI);
            }
        }
    }
}

// ---------------- launch ----------------
extern "C" void kernel_launch(void* const* d_in, const int* in_sizes, int n_in,
                              void* d_out, int out_size) {
    const float* x     = (const float*)d_in[0];
    const int*   ei    = (const int*)d_in[1];
    const float* fc_w  = (const float*)d_in[2];
    const float* fc_b  = (const float*)d_in[3];
    const float* convw = (const float*)d_in[4];
    const float* convb = (const float*)d_in[5];
    const float* gamma = (const float*)d_in[6];
    const float* beta  = (const float*)d_in[7];
    const float* clsw  = (const float*)d_in[8];
    const float* clsb  = (const float*)d_in[9];
    float* out = (float*)d_out;
    const int* row = ei;        // edge_index[0]
    const int* col = ei + EE;   // edge_index[1]

    const int smem_gemm = (64 * 128 + 128 * 129) * 4;   // 98816 B
    const int smem_cls  = (64 * 132 + 128 * 40) * 4;    // 54272 B
    cudaFuncSetAttribute(gemm128_kernel, cudaFuncAttributeMaxDynamicSharedMemorySize, smem_gemm);
    cudaFuncSetAttribute(gemm_cls_kernel, cudaFuncAttributeMaxDynamicSharedMemorySize, smem_cls);

    // ---- CSR build (counting sort by col) + normalization weights ----
    zero_cnt_kernel<<<(NN + 1023) / 1024, 1024>>>();
    compute_cnt_kernel<<<EE / 256, 256>>>(col);
    dinv_kernel<<<(NN + 255) / 256, 256>>>();
    scan1_kernel<<<SCAN_NB, 1024>>>();
    scan2_kernel<<<1, 128>>>();
    scan3_kernel<<<(NN + 255) / 256, 256>>>();
    scatter_kernel<<<EE / 256, 256>>>(row, col);

    const int gB = (NN + 63) / 64;          // 1563
    const int eltB = NN * 32 / 256;         // 12500

    // input projection + BN + relu, capture x0
    gemm128_kernel<<<gB, 256, smem_gemm>>>(x, 0, fc_w, fc_b);
    col_stats_kernel<<<STAT_BLOCKS, 128>>>();
    bn_finalize_kernel<<<1, 512>>>(gamma, beta);
    bn_apply_kernel<<<eltB, 256>>>(0);

    for (int l = 0; l < 3; l++) {
        spmm_csr_kernel<<<NN / 8, 256>>>();
        gemm128_kernel<<<gB, 256, smem_gemm>>>(nullptr, 1, convw + l * DD * DD, convb + l * DD);
        col_stats_kernel<<<STAT_BLOCKS, 128>>>();
        bn_finalize_kernel<<<1, 512>>>(gamma + (l + 1) * DD, beta + (l + 1) * DD);
        bn_apply_kernel<<<eltB, 256>>>(1);
    }

    gemm_cls_kernel<<<gB, 256, smem_cls>>>(clsw, clsb, out);
}

// round 9
// speedup vs baseline: 1.6908x; 1.0755x over previous
#include <cuda_runtime.h>
#include <cuda_fp16.h>

#define NN 100000
#define EE 1600000
#define DD 128
#define STAT_BLOCKS 1000  // NN / 100 rows per block
#define SCAN_NB 98        // ceil(NN / 1024)

// ---------------- scratch (device globals: no allocation allowed) ----------------
__device__ __align__(16) float g_deg[NN];            // dinv (float)
__device__ __align__(16) int   g_cnt[NN];            // int degree
__device__ __align__(16) int   g_offp[NN];           // per-block exclusive scan
__device__ __align__(16) int   g_off[NN + 1];        // CSR offsets
__device__ __align__(16) int   g_cur[NN];            // scatter cursors
__device__ __align__(16) int   g_bsum[128];          // scan block sums
__device__ __align__(16) int   g_bpre[128];          // scan block prefixes
__device__ __align__(16) int2  g_edge[EE];           // CSR: {row*32, val bits}
__device__ __align__(16) __half g_h[NN * DD];        // current activations (fp16)
__device__ __align__(16) __half g_x0[NN * DD];       // first embedding (fp16)
__device__ __align__(16) float g_tmp[NN * DD];       // GEMM output (pre-BN)
__device__ __align__(16) float g_agg[NN * DD];       // SPMM output (fp32)
__device__ __align__(16) float g_part[STAT_BLOCKS * 256]; // [sum(128)|sumsq(128)]
__device__ __align__(16) float g_scale[DD];
__device__ __align__(16) float g_shift[DD];

// ---------------- degree ----------------
__global__ void zero_cnt_kernel() {
    int i = blockIdx.x * blockDim.x + threadIdx.x;
    if (i < NN) g_cnt[i] = 0;
}

__global__ void compute_cnt_kernel(const int* __restrict__ col) {
    int e = blockIdx.x * blockDim.x + threadIdx.x;   // EE % 256 == 0
    atomicAdd(&g_cnt[col[e]], 1);
}

__global__ void dinv_kernel() {
    int i = blockIdx.x * blockDim.x + threadIdx.x;
    if (i < NN) {
        int d = g_cnt[i];
        g_deg[i] = d > 0 ? rsqrtf((float)d) : 0.f;
    }
}

// ---------------- prefix scan (3 phases) ----------------
__global__ void __launch_bounds__(1024) scan1_kernel() {
    __shared__ int sh[1024];
    int i = blockIdx.x * 1024 + threadIdx.x;
    int v = (i < NN) ? g_cnt[i] : 0;
    sh[threadIdx.x] = v;
    __syncthreads();
#pragma unroll
    for (int off = 1; off < 1024; off <<= 1) {
        int t = 0;
        if (threadIdx.x >= off) t = sh[threadIdx.x - off];
        __syncthreads();
        sh[threadIdx.x] += t;
        __syncthreads();
    }
    if (i < NN) g_offp[i] = sh[threadIdx.x] - v;     // exclusive within block
    if (threadIdx.x == 1023) g_bsum[blockIdx.x] = sh[1023];
}

__global__ void scan2_kernel() {                     // 1 block, 128 threads
    __shared__ int sh[128];
    int t = threadIdx.x;
    int v = (t < SCAN_NB) ? g_bsum[t] : 0;
    sh[t] = v;
    __syncthreads();
#pragma unroll
    for (int off = 1; off < 128; off <<= 1) {
        int u = 0;
        if (t >= off) u = sh[t - off];
        __syncthreads();
        sh[t] += u;
        __syncthreads();
    }
    if (t < SCAN_NB) g_bpre[t] = sh[t] - v;          // exclusive
}

__global__ void scan3_kernel() {
    int i = blockIdx.x * blockDim.x + threadIdx.x;
    if (i < NN) {
        g_off[i] = g_offp[i] + g_bpre[i >> 10];
        g_cur[i] = 0;
    }
    if (i == 0) g_off[NN] = EE;
}

// ---------------- CSR scatter (sort edges by col) + weight ----------------
__global__ void scatter_kernel(const int* __restrict__ row, const int* __restrict__ col) {
    int e = blockIdx.x * blockDim.x + threadIdx.x;   // EE % 256 == 0
    int r = row[e];
    int c = col[e];
    int p = g_off[c] + atomicAdd(&g_cur[c], 1);
    int2 ev;
    ev.x = r * 32;                                   // pre-scaled uint2 row base
    ev.y = __float_as_int(g_deg[c] * g_deg[r]);
    g_edge[p] = ev;
}

// ---------------- SPMM (gather, no atomics): one warp per destination node ----------------
__global__ void __launch_bounds__(256) spmm_csr_kernel() {
    int n = blockIdx.x * 8 + (threadIdx.x >> 5);     // NN % 8 == 0
    int lane = threadIdx.x & 31;
    int s = g_off[n];
    int e = g_off[n + 1];
    float4 acc = make_float4(0.f, 0.f, 0.f, 0.f);
#pragma unroll 4
    for (int p = s; p < e; p++) {
        int2 ev = __ldg(g_edge + p);                 // warp-uniform broadcast
        float v = __int_as_float(ev.y);
        uint2 hv = ((const uint2*)g_h)[ev.x + lane]; // 4 halves (8 B) gather
        float2 f01 = __half22float2(*(const __half2*)&hv.x);
        float2 f23 = __half22float2(*(const __half2*)&hv.y);
        acc.x += v * f01.x; acc.y += v * f01.y;
        acc.z += v * f23.x; acc.w += v * f23.y;
    }
    ((float4*)g_agg)[n * 32 + lane] = acc;
}

// ---------------- 128-wide SGEMM: g_tmp = A @ W^T + bias ----------------
__global__ void __launch_bounds__(256) gemm128_kernel(const float* __restrict__ Aext,
                                                      int useAgg,
                                                      const float* __restrict__ W,
                                                      const float* __restrict__ bias) {
    extern __shared__ float sh[];
    float* xs = sh;               // 64*128
    float* ws = sh + 64 * 128;    // 128*129 (transposed, padded: ws[k*129+n])
    const float* A = useAgg ? g_agg : Aext;
    int tid = threadIdx.x;
    int rowBase = blockIdx.x * 64;

#pragma unroll
    for (int i = 0; i < 64; i++) {        // stage W transposed (conflict-free: stride 129)
        int idx = i * 256 + tid;
        ws[(idx & 127) * 129 + (idx >> 7)] = W[idx];
    }
#pragma unroll
    for (int i = 0; i < 32; i++) {        // stage A tile
        int idx = i * 256 + tid;
        int r = rowBase + (idx >> 7);
        xs[idx] = (r < NN) ? A[r * DD + (idx & 127)] : 0.f;
    }
    __syncthreads();

    int tx = tid & 31;        // cols tx, tx+32, tx+64, tx+96
    int ty = tid >> 5;        // rows ty*8 .. ty*8+7
    float acc[8][4];
#pragma unroll
    for (int j = 0; j < 8; j++) { acc[j][0] = acc[j][1] = acc[j][2] = acc[j][3] = 0.f; }

    const float4* xs4 = (const float4*)xs + ty * 8 * 32;
    for (int k4 = 0; k4 < 32; k4++) {
        float w[4][4];
#pragma unroll
        for (int kk = 0; kk < 4; kk++) {
            const float* wr = ws + (k4 * 4 + kk) * 129 + tx;
            w[kk][0] = wr[0]; w[kk][1] = wr[32]; w[kk][2] = wr[64]; w[kk][3] = wr[96];
        }
#pragma unroll
        for (int j = 0; j < 8; j++) {
            float4 xv = xs4[j * 32 + k4];
            acc[j][0] += xv.x * w[0][0]; acc[j][1] += xv.x * w[0][1];
            acc[j][2] += xv.x * w[0][2]; acc[j][3] += xv.x * w[0][3];
            acc[j][0] += xv.y * w[1][0]; acc[j][1] += xv.y * w[1][1];
            acc[j][2] += xv.y * w[1][2]; acc[j][3] += xv.y * w[1][3];
            acc[j][0] += xv.z * w[2][0]; acc[j][1] += xv.z * w[2][1];
            acc[j][2] += xv.z * w[2][2]; acc[j][3] += xv.z * w[2][3];
            acc[j][0] += xv.w * w[3][0]; acc[j][1] += xv.w * w[3][1];
            acc[j][2] += xv.w * w[3][2]; acc[j][3] += xv.w * w[3][3];
        }
    }

    float b0 = __ldg(bias + tx), b1 = __ldg(bias + tx + 32);
    float b2 = __ldg(bias + tx + 64), b3 = __ldg(bias + tx + 96);
#pragma unroll
    for (int j = 0; j < 8; j++) {
        int r = rowBase + ty * 8 + j;
        if (r < NN) {
            float* o = g_tmp + r * DD + tx;
            o[0] = acc[j][0] + b0; o[32] = acc[j][1] + b1;
            o[64] = acc[j][2] + b2; o[96] = acc[j][3] + b3;
        }
    }
}

// ---------------- BN stats (two-stage, no atomics) ----------------
__global__ void col_stats_kernel() {
    int c = threadIdx.x;                 // 128 threads, one per column
    int r0 = blockIdx.x * 100;           // NN / STAT_BLOCKS
    float s = 0.f, s2 = 0.f;
#pragma unroll 4
    for (int r = r0; r < r0 + 100; r++) {
        float v = g_tmp[r * DD + c];
        s += v; s2 += v * v;
    }
    g_part[blockIdx.x * 256 + c] = s;
    g_part[blockIdx.x * 256 + 128 + c] = s2;
}

__global__ void bn_finalize_kernel(const float* __restrict__ gamma,
                                   const float* __restrict__ beta) {
    __shared__ float sh_s[512], sh_s2[512];
    int t = threadIdx.x;                 // 512 threads
    int c = t & 127, q = t >> 7;
    float s = 0.f, s2 = 0.f;
    for (int b = q; b < STAT_BLOCKS; b += 4) {
        s += g_part[b * 256 + c];
        s2 += g_part[b * 256 + 128 + c];
    }
    sh_s[t] = s; sh_s2[t] = s2;
    __syncthreads();
    if (q == 0) {
        s = sh_s[c] + sh_s[c + 128] + sh_s[c + 256] + sh_s[c + 384];
        s2 = sh_s2[c] + sh_s2[c + 128] + sh_s2[c + 256] + sh_s2[c + 384];
        const float invM = 1.0f / (float)NN;
        float mu = s * invM;
        float var = s2 * invM - mu * mu;
        float sc = gamma[c] * rsqrtf(var + 1e-5f);
        g_scale[c] = sc;
        g_shift[c] = beta[c] - mu * sc;
    }
}

// ---------------- BN apply + relu (+ residual); h, x0 stored fp16 ----------------
__global__ void bn_apply_kernel(int addRes) {
    int i = blockIdx.x * blockDim.x + threadIdx.x;   // NN*32 items of 4 cols
    int c4 = i & 31;
    float4 v = ((const float4*)g_tmp)[i];
    float4 sc = ((const float4*)g_scale)[c4];
    float4 shv = ((const float4*)g_shift)[c4];
    v.x = fmaxf(v.x * sc.x + shv.x, 0.f);
    v.y = fmaxf(v.y * sc.y + shv.y, 0.f);
    v.z = fmaxf(v.z * sc.z + shv.z, 0.f);
    v.w = fmaxf(v.w * sc.w + shv.w, 0.f);
    if (addRes) {
        uint2 x0p = ((const uint2*)g_x0)[i];
        float2 x01 = __half22float2(*(const __half2*)&x0p.x);
        float2 x23 = __half22float2(*(const __half2*)&x0p.y);
        v.x += x01.x; v.y += x01.y; v.z += x23.x; v.w += x23.y;
    }
    __half2 lo = __floats2half2_rn(v.x, v.y);
    __half2 hi = __floats2half2_rn(v.z, v.w);
    uint2 pack;
    pack.x = *(const unsigned*)&lo;
    pack.y = *(const unsigned*)&hi;
    if (!addRes) ((uint2*)g_x0)[i] = pack;           // first layer: capture residual
    ((uint2*)g_h)[i] = pack;
}

// ---------------- classifier: out = h @ cls_w^T + cls_b, [NN,40] ----------------
__global__ void __launch_bounds__(256) gemm_cls_kernel(const float* __restrict__ W,
                                                       const float* __restrict__ bias,
                                                       float* __restrict__ out) {
    extern __shared__ float sh[];
    float* xs = sh;               // 64*132 (padded)
    float* ws = sh + 64 * 132;    // 128*40 (transposed: ws[k*40+c])
    int tid = threadIdx.x;
    int rowBase = blockIdx.x * 64;

#pragma unroll
    for (int i = 0; i < 20; i++) {        // 40*128 = 5120 = 20*256
        int idx = i * 256 + tid;
        ws[(idx & 127) * 40 + (idx >> 7)] = W[idx];
    }
#pragma unroll
    for (int i = 0; i < 8; i++) {         // 64 rows * 32 uint2 = 2048
        int idx = i * 256 + tid;
        int r = rowBase + (idx >> 5);
        int u = idx & 31;                 // 4 halves per uint2
        float4 f;
        if (r < NN) {
            uint2 hv = ((const uint2*)g_h)[r * 32 + u];
            float2 f01 = __half22float2(*(const __half2*)&hv.x);
            float2 f23 = __half22float2(*(const __half2*)&hv.y);
            f = make_float4(f01.x, f01.y, f23.x, f23.y);
        } else f = make_float4(0.f, 0.f, 0.f, 0.f);
        float* dst = xs + (idx >> 5) * 132 + u * 4;
        dst[0] = f.x; dst[1] = f.y; dst[2] = f.z; dst[3] = f.w;
    }
    __syncthreads();

    int tx = tid & 7;     // cols tx + 8*c
    int ty = tid >> 3;    // rows ty*2, ty*2+1
    float acc[2][5];
#pragma unroll
    for (int j = 0; j < 2; j++)
#pragma unroll
        for (int c = 0; c < 5; c++) acc[j][c] = 0.f;

    const float* x0p = xs + (ty * 2) * 132;
    const float* x1p = x0p + 132;
#pragma unroll 4
    for (int k = 0; k < 128; k++) {
        float xv0 = x0p[k], xv1 = x1p[k];
        const float* wr = ws + k * 40 + tx;
#pragma unroll
        for (int c = 0; c < 5; c++) {
            float wv = wr[8 * c];
            acc[0][c] += xv0 * wv;
            acc[1][c] += xv1 * wv;
        }
    }
#pragma unroll
    for (int j = 0; j < 2; j++) {
        int r = rowBase + ty * 2 + j;
        if (r < NN) {
#pragma unroll
            for (int c = 0; c < 5; c++) {
                int colI = tx + 8 * c;
                out[r * 40 + colI] = acc[j][c] + __ldg(bias + colI);
            }
        }
    }
}

// ---------------- launch ----------------
extern "C" void kernel_launch(void* const* d_in, const int* in_sizes, int n_in,
                              void* d_out, int out_size) {
    const float* x     = (const float*)d_in[0];
    const int*   ei    = (const int*)d_in[1];
    const float* fc_w  = (const float*)d_in[2];
    const float* fc_b  = (const float*)d_in[3];
    const float* convw = (const float*)d_in[4];
    const float* convb = (const float*)d_in[5];
    const float* gamma = (const float*)d_in[6];
    const float* beta  = (const float*)d_in[7];
    const float* clsw  = (const float*)d_in[8];
    const float* clsb  = (const float*)d_in[9];
    float* out = (float*)d_out;
    const int* row = ei;        // edge_index[0]
    const int* col = ei + EE;   // edge_index[1]

    const int smem_gemm = (64 * 128 + 128 * 129) * 4;   // 98816 B
    const int smem_cls  = (64 * 132 + 128 * 40) * 4;    // 54272 B
    cudaFuncSetAttribute(gemm128_kernel, cudaFuncAttributeMaxDynamicSharedMemorySize, smem_gemm);
    cudaFuncSetAttribute(gemm_cls_kernel, cudaFuncAttributeMaxDynamicSharedMemorySize, smem_cls);

    // ---- CSR build (counting sort by col) + normalization weights ----
    zero_cnt_kernel<<<(NN + 1023) / 1024, 1024>>>();
    compute_cnt_kernel<<<EE / 256, 256>>>(col);
    dinv_kernel<<<(NN + 255) / 256, 256>>>();
    scan1_kernel<<<SCAN_NB, 1024>>>();
    scan2_kernel<<<1, 128>>>();
    scan3_kernel<<<(NN + 255) / 256, 256>>>();
    scatter_kernel<<<EE / 256, 256>>>(row, col);

    const int gB = (NN + 63) / 64;          // 1563
    const int eltB = NN * 32 / 256;         // 12500

    // input projection + BN + relu, capture x0
    gemm128_kernel<<<gB, 256, smem_gemm>>>(x, 0, fc_w, fc_b);
    col_stats_kernel<<<STAT_BLOCKS, 128>>>();
    bn_finalize_kernel<<<1, 512>>>(gamma, beta);
    bn_apply_kernel<<<eltB, 256>>>(0);

    for (int l = 0; l < 3; l++) {
        spmm_csr_kernel<<<NN / 8, 256>>>();
        gemm128_kernel<<<gB, 256, smem_gemm>>>(nullptr, 1, convw + l * DD * DD, convb + l * DD);
        col_stats_kernel<<<STAT_BLOCKS, 128>>>();
        bn_finalize_kernel<<<1, 512>>>(gamma + (l + 1) * DD, beta + (l + 1) * DD);
        bn_apply_kernel<<<eltB, 256>>>(1);
    }

    gemm_cls_kernel<<<gB, 256, smem_cls>>>(clsw, clsb, out);
}